// round 1
// baseline (speedup 1.0000x reference)
#include <cuda_runtime.h>
#include <stdint.h>

// ---------------------------------------------------------------------------
// Top-k (by |x|) masking, k = int(0.1 * n), n = 33,554,432.
// Strategy:
//   Pass 1 (full read): count keys above window [1.5,1.8); compact in-window
//           (key,idx) pairs to a global buffer (expected ~2.07M entries).
//   Select: histogram/refine entirely on the compacted buffer; exact 32-bit
//           threshold T plus index cutoff C for ties (lower index first).
//   Fallback (flag-gated, normally early-exits): full radix select if the
//           threshold is somehow outside the window or the buffer overflows.
//   Pass 2 (full read+write): out[i] = keep ? x[i] : 0.
// Deterministic: all compaction is order-free downstream (histograms + min
// selection), tie-break is by smallest index.
// ---------------------------------------------------------------------------

#define KEY_WLO 0x3FC00000u          // bits(1.5f)
#define KEY_WUP 0x3FE66600u          // just under bits(1.8f), 512-aligned
#define WSHIFT  9
#define WBINS   ((KEY_WUP - KEY_WLO) >> WSHIFT)   // 4915
#define WCAP    3500000
#define FCAP    32768
#define STAGE_CAP   4096
#define STAGE_FLUSH 3072

__device__ unsigned g_winKey[WCAP];
__device__ unsigned g_winIdx[WCAP];
__device__ unsigned g_fineHist[WBINS];
__device__ unsigned g_hist16[32768];
__device__ unsigned g_finKey[FCAP];
__device__ unsigned g_finIdx[FCAP];
__device__ unsigned g_cntAbove, g_winCount, g_finCount, g_flag;
__device__ unsigned g_base, g_need, g_nbins;
__device__ unsigned g_binLo, g_need2;
__device__ unsigned g_T, g_C;

// ---------------- zero scratch (runs every launch; graph-replay safe) ------
__global__ void k_zero() {
    int i = blockIdx.x * blockDim.x + threadIdx.x;
    int stride = gridDim.x * blockDim.x;
    for (int j = i; j < (int)WBINS; j += stride) g_fineHist[j] = 0;
    for (int j = i; j < 32768; j += stride) g_hist16[j] = 0;
    if (i == 0) { g_cntAbove = 0; g_winCount = 0; g_finCount = 0; g_flag = 0; }
}

// ---------------- pass 1: count-above + window compaction ------------------
__global__ __launch_bounds__(256) void k_scan(const float4* __restrict__ x,
                                              int n4, int n) {
    __shared__ uint2 stage[STAGE_CAP];               // 32 KB
    __shared__ unsigned s_cnt, s_base, s_above;
    const int tid = threadIdx.x;
    if (tid == 0) { s_cnt = 0; s_above = 0; }
    __syncthreads();

    unsigned above = 0;
    long long gs = (long long)gridDim.x * blockDim.x;
    long long i0 = (long long)blockIdx.x * blockDim.x + tid;
    int iters = (int)((n4 + gs - 1) / gs);

    for (int it = 0; it < iters; ++it) {
        long long i = i0 + (long long)it * gs;
        if (i < n4) {
            float4 v = x[i];
            unsigned bi = (unsigned)(i << 2);
            float vals[4] = { v.x, v.y, v.z, v.w };
            #pragma unroll
            for (int c = 0; c < 4; c++) {
                unsigned key = __float_as_uint(vals[c]) & 0x7fffffffu;
                if (key >= KEY_WUP) {
                    above++;
                } else if (key >= KEY_WLO) {
                    unsigned p = atomicAdd(&s_cnt, 1);
                    if (p < STAGE_CAP) stage[p] = make_uint2(key, bi + c);
                }
            }
        }
        __syncthreads();
        if (s_cnt >= STAGE_FLUSH) {                  // uniform branch per block
            if (tid == 0) s_base = atomicAdd(&g_winCount, s_cnt);
            __syncthreads();
            unsigned cnt = s_cnt, b = s_base;
            if (cnt <= STAGE_CAP && b + cnt <= WCAP) {
                for (unsigned j = tid; j < cnt; j += blockDim.x) {
                    uint2 e = stage[j];
                    g_winKey[b + j] = e.x;
                    g_winIdx[b + j] = e.y;
                }
            } else if (tid == 0) {
                g_flag = 1;
            }
            __syncthreads();
            if (tid == 0) s_cnt = 0;
            __syncthreads();
        }
    }

    // scalar tail (n % 4), block 0 only — no syncs inside
    if (blockIdx.x == 0) {
        const float* xs = (const float*)x;
        for (int e = n4 * 4 + tid; e < n; e += blockDim.x) {
            unsigned key = __float_as_uint(xs[e]) & 0x7fffffffu;
            if (key >= KEY_WUP) above++;
            else if (key >= KEY_WLO) {
                unsigned p = atomicAdd(&s_cnt, 1);
                if (p < STAGE_CAP) stage[p] = make_uint2(key, (unsigned)e);
            }
        }
    }
    __syncthreads();

    if (s_cnt > 0) {                                 // final flush (uniform)
        if (tid == 0) s_base = atomicAdd(&g_winCount, s_cnt);
        __syncthreads();
        unsigned cnt = s_cnt, b = s_base;
        if (cnt <= STAGE_CAP && b + cnt <= WCAP) {
            for (unsigned j = tid; j < cnt; j += blockDim.x) {
                uint2 e = stage[j];
                g_winKey[b + j] = e.x;
                g_winIdx[b + j] = e.y;
            }
        } else if (tid == 0) {
            g_flag = 1;
        }
    }
    __syncthreads();
    atomicAdd(&s_above, above);
    __syncthreads();
    if (tid == 0 && s_above) atomicAdd(&g_cntAbove, s_above);
}

// ---------------- decide fast path vs fallback -----------------------------
__global__ void k_decide(unsigned k) {
    if (blockIdx.x == 0 && threadIdx.x == 0) {
        unsigned above = g_cntAbove, wc = g_winCount;
        if (g_flag == 0 && above < k && above + wc >= k && wc <= WCAP) {
            g_base = KEY_WLO; g_need = k - above; g_nbins = WBINS;
        } else {
            g_flag = 1; g_winCount = 0;
        }
    }
}

// ---------------- fallback path (normally early-exits) ---------------------
__global__ void k_fb_hist(const float* __restrict__ x, int n) {
    if (g_flag == 0) return;
    int i0 = blockIdx.x * blockDim.x + threadIdx.x;
    int gs = gridDim.x * blockDim.x;
    for (int i = i0; i < n; i += gs) {
        unsigned key = __float_as_uint(x[i]) & 0x7fffffffu;
        atomicAdd(&g_hist16[key >> 16], 1);
    }
}

__global__ void k_fb_scan(unsigned k) {
    if (g_flag == 0) return;
    __shared__ unsigned s_sum[256];
    int t = threadIdx.x;
    unsigned sum = 0;
    for (int b = t * 128; b < (t + 1) * 128; b++) sum += g_hist16[b];
    s_sum[t] = sum;
    __syncthreads();
    if (t == 0) {
        unsigned cum = 0;
        for (int c = 255; c >= 0; c--) {
            if (cum + s_sum[c] >= k) {
                for (int b = (c + 1) * 128 - 1; b >= c * 128; b--) {
                    unsigned h = g_hist16[b];
                    if (cum + h >= k) {
                        g_base = (unsigned)b << 16;
                        g_need = k - cum;
                        g_nbins = 65536u >> WSHIFT;   // 128
                        return;
                    }
                    cum += h;
                }
            }
            cum += s_sum[c];
        }
    }
}

__global__ void k_fb_compact(const float* __restrict__ x, int n) {
    if (g_flag == 0) return;
    unsigned B = g_base;
    int i0 = blockIdx.x * blockDim.x + threadIdx.x;
    int gs = gridDim.x * blockDim.x;
    for (int i = i0; i < n; i += gs) {
        unsigned key = __float_as_uint(x[i]) & 0x7fffffffu;
        if ((key & 0xFFFF0000u) == B) {
            unsigned p = atomicAdd(&g_winCount, 1);
            if (p < WCAP) { g_winKey[p] = key; g_winIdx[p] = (unsigned)i; }
        }
    }
}

// ---------------- fine histogram on compacted buffer -----------------------
__global__ void k_fine() {
    unsigned wc = min(g_winCount, (unsigned)WCAP);
    unsigned base = g_base, nb = g_nbins;
    unsigned i0 = blockIdx.x * blockDim.x + threadIdx.x;
    unsigned gs = gridDim.x * blockDim.x;
    for (unsigned i = i0; i < wc; i += gs) {
        unsigned b = (g_winKey[i] - base) >> WSHIFT;
        if (b < nb) atomicAdd(&g_fineHist[b], 1);
    }
}

__global__ void k_fine_scan() {
    __shared__ unsigned s_sum[256];
    int t = threadIdx.x;
    unsigned nb = g_nbins, need = g_need;
    unsigned chunk = (nb + 255) / 256;
    unsigned lo = t * chunk, hi = min(nb, (unsigned)(t + 1) * chunk);
    unsigned sum = 0;
    for (unsigned b = lo; b < hi; b++) sum += g_fineHist[b];
    s_sum[t] = sum;
    __syncthreads();
    if (t == 0) {
        unsigned cum = 0;
        for (int c = 255; c >= 0; c--) {
            unsigned clo = c * chunk;
            if (clo >= nb) continue;
            unsigned chi = min(nb, (unsigned)(c + 1) * chunk);
            if (cum + s_sum[c] >= need) {
                for (int b = (int)chi - 1; b >= (int)clo; b--) {
                    unsigned h = g_fineHist[b];
                    if (cum + h >= need) {
                        g_binLo = g_base + ((unsigned)b << WSHIFT);
                        g_need2 = need - cum;
                        return;
                    }
                    cum += h;
                }
            }
            cum += s_sum[c];
        }
    }
}

// ---------------- collect final 512-wide bin -------------------------------
__global__ void k_collect() {
    unsigned wc = min(g_winCount, (unsigned)WCAP);
    unsigned lo = g_binLo, hiX = lo + 512;
    unsigned i0 = blockIdx.x * blockDim.x + threadIdx.x;
    unsigned gs = gridDim.x * blockDim.x;
    for (unsigned i = i0; i < wc; i += gs) {
        unsigned key = g_winKey[i];
        if (key >= lo && key < hiX) {
            unsigned p = atomicAdd(&g_finCount, 1);
            if (p < FCAP) { g_finKey[p] = key; g_finIdx[p] = g_winIdx[i]; }
        }
    }
}

// ---------------- exact threshold + deterministic tie cutoff ---------------
__global__ __launch_bounds__(512) void k_final() {
    __shared__ unsigned h[512];
    __shared__ unsigned tlist[2048];
    __shared__ unsigned s_tcnt, sT, sRem;
    int t = threadIdx.x;
    for (int j = t; j < 512; j += blockDim.x) h[j] = 0;
    if (t == 0) s_tcnt = 0;
    __syncthreads();
    unsigned fc = min(g_finCount, (unsigned)FCAP);
    for (unsigned i = t; i < fc; i += blockDim.x)
        atomicAdd(&h[g_finKey[i] & 511u], 1);
    __syncthreads();
    if (t == 0) {
        unsigned need2 = g_need2, cum = 0;
        for (int v = 511; v >= 0; v--) {
            unsigned c = h[v];
            if (cum + c >= need2) {
                sT = g_binLo | (unsigned)v;
                sRem = need2 - cum;
                break;
            }
            cum += c;
        }
    }
    __syncthreads();
    unsigned T = sT;
    for (unsigned i = t; i < fc; i += blockDim.x) {
        if (g_finKey[i] == T) {
            unsigned p = atomicAdd(&s_tcnt, 1);
            if (p < 2048) tlist[p] = g_finIdx[i];
        }
    }
    __syncthreads();
    if (t == 0) {
        unsigned m = min(s_tcnt, 2048u), rem = sRem;
        unsigned C;
        if (rem >= m) {
            C = 0xFFFFFFFFu;                 // keep all ties
        } else {
            // rem-th smallest index among ties (jax top_k: lower index first)
            long long prev = -1; C = 0;
            for (unsigned r = 0; r < rem; r++) {
                unsigned best = 0xFFFFFFFFu;
                for (unsigned j = 0; j < m; j++) {
                    unsigned v = tlist[j];
                    if ((long long)v > prev && v < best) best = v;
                }
                C = best; prev = (long long)best;
            }
        }
        g_T = T; g_C = C;
    }
}

// ---------------- pass 2: apply mask ---------------------------------------
__global__ __launch_bounds__(256) void k_apply(const float4* __restrict__ x,
                                               float4* __restrict__ o,
                                               int n4, int n) {
    unsigned T = g_T, C = g_C;
    int i0 = blockIdx.x * blockDim.x + threadIdx.x;
    int gs = gridDim.x * blockDim.x;
    for (int i = i0; i < n4; i += gs) {
        float4 v = x[i];
        unsigned bi = (unsigned)i << 2;
        unsigned k0 = __float_as_uint(v.x) & 0x7fffffffu;
        unsigned k1 = __float_as_uint(v.y) & 0x7fffffffu;
        unsigned k2 = __float_as_uint(v.z) & 0x7fffffffu;
        unsigned k3 = __float_as_uint(v.w) & 0x7fffffffu;
        v.x = (k0 > T || (k0 == T && bi + 0 <= C)) ? v.x : 0.0f;
        v.y = (k1 > T || (k1 == T && bi + 1 <= C)) ? v.y : 0.0f;
        v.z = (k2 > T || (k2 == T && bi + 2 <= C)) ? v.z : 0.0f;
        v.w = (k3 > T || (k3 == T && bi + 3 <= C)) ? v.w : 0.0f;
        o[i] = v;
    }
    if (blockIdx.x == 0) {
        const float* xs = (const float*)x;
        float* os = (float*)o;
        for (int e = n4 * 4 + threadIdx.x; e < n; e += blockDim.x) {
            unsigned kk = __float_as_uint(xs[e]) & 0x7fffffffu;
            os[e] = (kk > T || (kk == T && (unsigned)e <= C)) ? xs[e] : 0.0f;
        }
    }
}

// ---------------------------------------------------------------------------
extern "C" void kernel_launch(void* const* d_in, const int* in_sizes, int n_in,
                              void* d_out, int out_size) {
    const float* x = (const float*)d_in[0];
    int n = in_sizes[0];
    int n4 = n / 4;
    unsigned k = (unsigned)(0.1 * (double)n);   // matches int(RATIO * n)

    k_zero<<<128, 256>>>();
    k_scan<<<592, 256>>>((const float4*)x, n4, n);
    k_decide<<<1, 32>>>(k);
    // fallback chain (early-exits when fast path valid)
    k_fb_hist<<<592, 256>>>(x, n);
    k_fb_scan<<<1, 256>>>(k);
    k_fb_compact<<<592, 256>>>(x, n);
    // selection on compacted buffer
    k_fine<<<296, 256>>>();
    k_fine_scan<<<1, 256>>>();
    k_collect<<<296, 256>>>();
    k_final<<<1, 512>>>();
    // apply
    k_apply<<<1184, 256>>>((const float4*)x, (float4*)d_out, n4, n);
}

// round 6
// speedup vs baseline: 2.5619x; 2.5619x over previous
#include <cuda_runtime.h>
#include <stdint.h>

// ---------------------------------------------------------------------------
// Top-k-by-|x| masking. n = 33,554,432, k = int(0.1*n) = 3,355,443.
// Threshold for N(0,1) input lies at |x| ~ 1.6449 +- ~60 sigma inside the
// narrow window [1.62988, 1.66016]. Pass 1 streams x once: counts keys above
// the window and compacts in-window (key,idx) pairs into per-warp private
// segments (NO atomics in the hot path: ballot/popc prefix + uniform register
// counter), plus a 496-bin shared histogram (spread-address atomics, cheap).
// Selection then runs entirely on the ~1.7MB compacted buffer. Exact 32-bit
// threshold T and tie cutoff C (lowest-index-first, matching jax top_k).
// A single-block, flag-gated exact fallback guards the (never-taken) case
// where the threshold falls outside the window. Scratch is self-cleaning:
// every kernel re-zeros what it consumed, so no zeroing kernel is needed and
// graph replays are deterministic.
// Launches: pass1, select, collect, final, fallback, apply  (6 total).
// ---------------------------------------------------------------------------

#define KEY_NLO 0x3FD0A000u            // bits(1.6298828f)
#define KEY_NUP 0x3FD48000u            // bits(1.6601562f)
#define BSHIFT  9
#define NBINS   ((KEY_NUP - KEY_NLO) >> BSHIFT)   // 496
#define NBLK    592
#define NTHR    512
#define WPB     (NTHR / 32)            // 16 warps per block
#define NWARP   (NBLK * WPB)           // 9472 grid warps / segments
#define SEGCAP  128                    // per-warp segment capacity (mean ~22)
#define FCAP    65536
#define TCAP    2048

__device__ uint2    g_seg[NWARP * SEGCAP];   // ~9.7 MB
__device__ unsigned g_segCnt[NWARP];
__device__ unsigned g_hist[NBINS];           // zeroed by k_select after read
__device__ unsigned g_cntAbove;              // zeroed by k_select after read
__device__ unsigned g_finCount;              // zeroed by k_final / k_fallback
__device__ uint2    g_fin[FCAP];
__device__ unsigned g_flag, g_binLo, g_need2;
__device__ unsigned g_T, g_C;

// ---------------- pass 1: count-above + per-warp window compaction ---------
__global__ __launch_bounds__(NTHR) void k_pass1(const float4* __restrict__ x,
                                                int n4, int iters) {
    __shared__ unsigned sh[NBINS];
    __shared__ unsigned sAb;
    for (int j = threadIdx.x; j < (int)NBINS; j += NTHR) sh[j] = 0;
    if (threadIdx.x == 0) sAb = 0;
    __syncthreads();

    const int lane = threadIdx.x & 31;
    const unsigned lmask = (1u << lane) - 1u;
    const int w = blockIdx.x * WPB + (threadIdx.x >> 5);
    const int T = NBLK * NTHR;
    const int i0 = blockIdx.x * NTHR + threadIdx.x;

    unsigned base = 0;                 // uniform across warp (ballot-derived)
    unsigned above = 0;

    for (int it = 0; it < iters; ++it) {
        int ib = i0 + it * 4 * T;
        float4 v[4];
        #pragma unroll
        for (int j = 0; j < 4; j++) {  // batch loads: MLP = 4x16B per thread
            int i = ib + j * T;
            v[j] = (i < n4) ? __ldg(&x[i]) : make_float4(0.f, 0.f, 0.f, 0.f);
        }
        #pragma unroll
        for (int j = 0; j < 4; j++) {
            int i = ib + j * T;
            bool valid = (i < n4);
            unsigned bi = (unsigned)i << 2;
            float vv[4] = { v[j].x, v[j].y, v[j].z, v[j].w };
            #pragma unroll
            for (int c = 0; c < 4; c++) {
                unsigned key = __float_as_uint(vv[c]) & 0x7fffffffu;
                if (valid && key >= KEY_NUP) above++;
                bool inw = valid && (key - KEY_NLO) < (KEY_NUP - KEY_NLO);
                unsigned m = __ballot_sync(0xffffffffu, inw);
                if (inw) {
                    unsigned pos = base + __popc(m & lmask);
                    if (pos < SEGCAP)
                        g_seg[w * SEGCAP + pos] = make_uint2(key, bi + c);
                    atomicAdd(&sh[(key - KEY_NLO) >> BSHIFT], 1u);
                }
                base += __popc(m);
            }
        }
    }

    // warp-reduce the above count, one shared add per warp, one global / block
    #pragma unroll
    for (int o = 16; o; o >>= 1) above += __shfl_down_sync(0xffffffffu, above, o);
    if (lane == 0) {
        g_segCnt[w] = min(base, (unsigned)SEGCAP);   // capped => overflow detectable
        if (above) atomicAdd(&sAb, above);
    }
    __syncthreads();
    if (threadIdx.x == 0 && sAb) atomicAdd(&g_cntAbove, sAb);
    for (int j = threadIdx.x; j < (int)NBINS; j += NTHR)
        if (sh[j]) atomicAdd(&g_hist[j], sh[j]);
}

// ---------------- select: find 512-wide bin; decide fast path --------------
__global__ __launch_bounds__(NTHR) void k_select(unsigned k, unsigned nmod4) {
    __shared__ unsigned sh[NBINS];
    __shared__ unsigned sSum;
    int t = threadIdx.x;
    if (t == 0) sSum = 0;
    if (t < (int)NBINS) { sh[t] = g_hist[t]; g_hist[t] = 0; }   // read + clean
    unsigned s = 0;
    for (int j = t; j < NWARP; j += NTHR) s += g_segCnt[j];
    __syncthreads();
    if (s) atomicAdd(&sSum, s);
    __syncthreads();
    if (t == 0) {
        unsigned above = g_cntAbove; g_cntAbove = 0;             // read + clean
        unsigned tot = 0;
        for (int b = 0; b < (int)NBINS; b++) tot += sh[b];
        unsigned flag = 0;
        if (nmod4) flag = 1;                    // scalar tail -> exact fallback
        if (sSum != tot) flag = 1;              // a segment overflowed
        if (above >= k) flag = 1;               // threshold above window
        if (above + tot < k) flag = 1;          // threshold below window
        if (!flag) {
            unsigned need = k - above, cum = 0;
            int b = (int)NBINS - 1;
            for (; b > 0; b--) {
                if (cum + sh[b] >= need) break;
                cum += sh[b];
            }
            g_binLo = KEY_NLO + ((unsigned)b << BSHIFT);
            g_need2 = need - cum;               // >= 1 by construction
        }
        g_flag = flag;
    }
}

// ---------------- collect final 512-wide bin from segments -----------------
__global__ __launch_bounds__(NTHR) void k_collect() {
    if (g_flag) return;
    unsigned lo = g_binLo, hi = lo + 512u;
    int w = blockIdx.x * WPB + (threadIdx.x >> 5);
    int lane = threadIdx.x & 31;
    unsigned cnt = g_segCnt[w];
    for (unsigned j = lane; j < cnt; j += 32) {
        uint2 e = g_seg[w * SEGCAP + j];
        if (e.x >= lo && e.x < hi) {
            unsigned p = atomicAdd(&g_finCount, 1u);   // ~420 total: trivial
            if (p < FCAP) g_fin[p] = e;
        }
    }
}

// ---------------- exact threshold T + deterministic tie cutoff C -----------
__global__ __launch_bounds__(512) void k_final() {
    __shared__ unsigned h[512];
    __shared__ unsigned tlist[TCAP];
    __shared__ unsigned sT, sRem, sTc;
    int t = threadIdx.x;
    h[t] = 0;
    if (t == 0) { sTc = 0; sRem = 1; sT = g_binLo; }
    __syncthreads();
    unsigned fc = g_finCount;
    if (t == 0) {
        g_finCount = 0;                                  // leave clean
        if (fc > FCAP) g_flag = 1;                       // cannot resolve here
    }
    if (fc > FCAP) fc = FCAP;
    unsigned lo = g_binLo;
    for (unsigned i = t; i < fc; i += 512)
        atomicAdd(&h[g_fin[i].x & 511u], 1u);
    __syncthreads();
    if (t == 0) {
        unsigned need2 = g_need2, cum = 0;
        for (int vb = 511; vb >= 0; vb--) {
            unsigned c = h[vb];
            if (cum + c >= need2) { sT = lo | (unsigned)vb; sRem = need2 - cum; break; }
            cum += c;
        }
    }
    __syncthreads();
    unsigned T = sT;
    for (unsigned i = t; i < fc; i += 512) {
        if (g_fin[i].x == T) {
            unsigned p = atomicAdd(&sTc, 1u);
            if (p < TCAP) tlist[p] = g_fin[i].y;
        }
    }
    __syncthreads();
    if (t == 0) {
        unsigned m = min(sTc, (unsigned)TCAP), rem = sRem, C = 0;
        if (sTc > TCAP) g_flag = 1;
        if (rem >= m) {
            C = 0xFFFFFFFFu;                             // keep all ties
        } else {
            long long prev = -1;                         // rem-th smallest index
            for (unsigned r = 0; r < rem; r++) {
                unsigned best = 0xFFFFFFFFu;
                for (unsigned j = 0; j < m; j++) {
                    unsigned v = tlist[j];
                    if ((long long)v > prev && v < best) best = v;
                }
                C = best; prev = (long long)best;
            }
        }
        g_T = T; g_C = C;
    }
}

// ---------------- exact single-block fallback (flag-gated, never taken) ----
__global__ __launch_bounds__(1024) void k_fallback(const float* __restrict__ x,
                                                   int n, unsigned k) {
    if (g_flag == 0) return;
    __shared__ unsigned sT, sRem;
    __shared__ unsigned swarp[32];
    int t = threadIdx.x;
    if (t == 0) sT = 0;
    __syncthreads();
    // bitwise search for T = k-th largest key: 31 full passes (exact, slow, unused)
    for (int b = 30; b >= 0; b--) {
        unsigned cand = sT | (1u << b);
        unsigned cnt = 0;
        for (int i = t; i < n; i += 1024)
            cnt += ((__float_as_uint(x[i]) & 0x7fffffffu) >= cand);
        #pragma unroll
        for (int o = 16; o; o >>= 1) cnt += __shfl_down_sync(0xffffffffu, cnt, o);
        if ((t & 31) == 0) swarp[t >> 5] = cnt;
        __syncthreads();
        if (t == 0) {
            unsigned tot = 0;
            for (int j = 0; j < 32; j++) tot += swarp[j];
            if (tot >= k) sT = cand;
        }
        __syncthreads();
    }
    unsigned T = sT;
    {   // rem = k - count(key > T)
        unsigned cnt = 0;
        for (int i = t; i < n; i += 1024)
            cnt += ((__float_as_uint(x[i]) & 0x7fffffffu) > T);
        #pragma unroll
        for (int o = 16; o; o >>= 1) cnt += __shfl_down_sync(0xffffffffu, cnt, o);
        if ((t & 31) == 0) swarp[t >> 5] = cnt;
        __syncthreads();
        if (t == 0) {
            unsigned tot = 0;
            for (int j = 0; j < 32; j++) tot += swarp[j];
            sRem = k - tot;
            g_finCount = 0;
        }
        __syncthreads();
    }
    for (int i = t; i < n; i += 1024) {
        if ((__float_as_uint(x[i]) & 0x7fffffffu) == T) {
            unsigned p = atomicAdd(&g_finCount, 1u);
            if (p < FCAP) g_fin[p] = make_uint2(T, (unsigned)i);
        }
    }
    __syncthreads();
    if (t == 0) {
        unsigned m = min(g_finCount, (unsigned)FCAP);
        unsigned rem = sRem, C = 0;
        if (rem >= m) {
            C = 0xFFFFFFFFu;
        } else {
            long long prev = -1;
            for (unsigned r = 0; r < rem; r++) {
                unsigned best = 0xFFFFFFFFu;
                for (unsigned j = 0; j < m; j++) {
                    unsigned v = g_fin[j].y;
                    if ((long long)v > prev && v < best) best = v;
                }
                C = best; prev = (long long)best;
            }
        }
        g_T = T; g_C = C;
        g_finCount = 0;                                  // leave clean
    }
}

// ---------------- pass 2: apply mask (pure stream, MLP=4) ------------------
__global__ __launch_bounds__(256) void k_apply(const float4* __restrict__ x,
                                               float4* __restrict__ o,
                                               int n4, int n) {
    unsigned T = g_T, C = g_C;
    int stride = gridDim.x * blockDim.x;
    int i0 = blockIdx.x * blockDim.x + threadIdx.x;
    float4 v[4]; bool val[4];
    #pragma unroll
    for (int j = 0; j < 4; j++) {
        int i = i0 + j * stride;
        val[j] = (i < n4);
        v[j] = val[j] ? __ldg(&x[i]) : make_float4(0.f, 0.f, 0.f, 0.f);
    }
    #pragma unroll
    for (int j = 0; j < 4; j++) {
        int i = i0 + j * stride;
        if (val[j]) {
            unsigned bi = (unsigned)i << 2;
            unsigned k0 = __float_as_uint(v[j].x) & 0x7fffffffu;
            unsigned k1 = __float_as_uint(v[j].y) & 0x7fffffffu;
            unsigned k2 = __float_as_uint(v[j].z) & 0x7fffffffu;
            unsigned k3 = __float_as_uint(v[j].w) & 0x7fffffffu;
            v[j].x = (k0 > T || (k0 == T && bi + 0 <= C)) ? v[j].x : 0.0f;
            v[j].y = (k1 > T || (k1 == T && bi + 1 <= C)) ? v[j].y : 0.0f;
            v[j].z = (k2 > T || (k2 == T && bi + 2 <= C)) ? v[j].z : 0.0f;
            v[j].w = (k3 > T || (k3 == T && bi + 3 <= C)) ? v[j].w : 0.0f;
            o[i] = v[j];
        }
    }
    if (blockIdx.x == 0) {                               // scalar tail (n%4)
        const float* xs = (const float*)x;
        float* os = (float*)o;
        for (int e = n4 * 4 + threadIdx.x; e < n; e += 256) {
            unsigned kk = __float_as_uint(xs[e]) & 0x7fffffffu;
            os[e] = (kk > T || (kk == T && (unsigned)e <= C)) ? xs[e] : 0.0f;
        }
    }
}

// ---------------------------------------------------------------------------
extern "C" void kernel_launch(void* const* d_in, const int* in_sizes, int n_in,
                              void* d_out, int out_size) {
    const float* x = (const float*)d_in[0];
    int n = in_sizes[0];
    int n4 = n / 4;
    unsigned k = (unsigned)(0.1 * (double)n);            // matches int(0.1*n)

    int totT = NBLK * NTHR;
    int iters = (n4 + 4 * totT - 1) / (4 * totT);
    int applyGrid = (n4 + 256 * 4 - 1) / (256 * 4);
    if (applyGrid < 1) applyGrid = 1;

    k_pass1  <<<NBLK, NTHR>>>((const float4*)x, n4, iters);
    k_select <<<1, NTHR>>>(k, (unsigned)(n & 3));
    k_collect<<<NBLK, NTHR>>>();
    k_final  <<<1, 512>>>();
    k_fallback<<<1, 1024>>>(x, n, k);
    k_apply  <<<applyGrid, 256>>>((const float4*)x, (float4*)d_out, n4, n);
}